// round 5
// baseline (speedup 1.0000x reference)
#include <cuda_runtime.h>
#include <math.h>

#define D     1024
#define D4    256          // D / 4
#define NMAT  2
#define RC    16           // row chunks for the small matvec kernels (64 rows each)
#define K3B   296          // blocks per matrix for the main streaming pass
#define MAXBLK 320
#define BG    16           // reduction bgroups
#define BPG   19           // partials per bgroup (16*19 = 304 >= 296, guarded)

// ---------------- static device scratch (no allocation allowed) ----------------
__device__ float  g_bw_part[NMAT][RC][D];
__device__ float  g_bw[NMAT][D];
__device__ float4 g_acc_part[NMAT][MAXBLK][D4];
__device__ float  g_wsum_part[NMAT][MAXBLK];
__device__ float  g_acc2[NMAT][BG][D];
__device__ float  g_wsum2[NMAT][BG];
__device__ float  g_vec[NMAT][D];            // normalized sum_output
__device__ float  g_res_part[NMAT][RC][D];

// ---------------- k1: partial b_w = b_alpha^T @ W_alpha ----------------
// grid (4 colgroups, RC rowchunks of 64, 2 mats), block 256
__global__ void k1_bw_partial(const float* __restrict__ Wa_in,  const float* __restrict__ b_in,
                              const float* __restrict__ Wa_out, const float* __restrict__ b_out) {
    const int colg = blockIdx.x, rc = blockIdx.y, mat = blockIdx.z;
    const float* __restrict__ W  = mat ? Wa_out : Wa_in;
    const float* __restrict__ bv = mat ? b_out  : b_in;
    __shared__ float s_b[64];
    const int tid = threadIdx.x;
    if (tid < 64) s_b[tid] = bv[rc * 64 + tid];
    __syncthreads();
    const int col = colg * 256 + tid;
    const float* __restrict__ Wp = W + (size_t)(rc * 64) * D + col;
    float acc = 0.f;
#pragma unroll 16
    for (int r = 0; r < 64; r++) acc += s_b[r] * __ldg(Wp + (size_t)r * D);
    g_bw_part[mat][rc][col] = acc;
}

// ---------------- k2: reduce b_w partials ----------------
// grid (4, 2), block 256
__global__ void k2_bw_reduce() {
    const int mat = blockIdx.y;
    const int col = blockIdx.x * 256 + threadIdx.x;
    float s = 0.f;
#pragma unroll
    for (int rc = 0; rc < RC; rc++) s += g_bw_part[mat][rc][col];
    g_bw[mat][col] = s;
}

// ---------------- k3: fused main pass (2-row software pipeline) ----------------
// One read of X: per row j compute s = X_j . b_w, w = exp(s), acc += w * X_j, wsum += w.
// warp-per-row, float4 loads, two rows in flight (16 LDG.128/warp/iter), interleaved
// shfl chains. grid (K3B, 2), block 256 (8 warps)
__global__ void __launch_bounds__(256, 2)
k3_main(const float* __restrict__ Xin, const float* __restrict__ Xout, int N) {
    const int mat  = blockIdx.y;
    const float4* __restrict__ X = (const float4*)(mat ? Xout : Xin);
    const int tid  = threadIdx.x;
    const int lane = tid & 31;
    const int wid  = tid >> 5;

    __shared__ float4 s_bw[D4];
    __shared__ float4 s_wacc[8][D4];
    __shared__ float  s_wsum[8];

    s_bw[tid] = ((const float4*)g_bw[mat])[tid];

    const int rpb = (N + K3B - 1) / K3B;      // 169
    const int r0  = blockIdx.x * rpb;
    const int r1  = min(N, r0 + rpb);

    float4 acc[8];
#pragma unroll
    for (int k = 0; k < 8; k++) acc[k] = make_float4(0.f, 0.f, 0.f, 0.f);
    float wsum = 0.f;
    __syncthreads();

    int r = r0 + wid;
    // main: two rows per iteration -> 16 independent LDG.128, 2 interleaved shfl chains
    for (; r + 8 < r1; r += 16) {
        const float4* __restrict__ xra = X + (size_t)r * D4;
        const float4* __restrict__ xrb = X + (size_t)(r + 8) * D4;
        float4 xa[8], xb[8];
#pragma unroll
        for (int k = 0; k < 8; k++) xa[k] = __ldg(xra + lane + 32 * k);
#pragma unroll
        for (int k = 0; k < 8; k++) xb[k] = __ldg(xrb + lane + 32 * k);
        float da = 0.f, db = 0.f;
#pragma unroll
        for (int k = 0; k < 8; k++) {
            const float4 b = s_bw[lane + 32 * k];
            da += xa[k].x * b.x + xa[k].y * b.y + xa[k].z * b.z + xa[k].w * b.w;
            db += xb[k].x * b.x + xb[k].y * b.y + xb[k].z * b.z + xb[k].w * b.w;
        }
#pragma unroll
        for (int o = 16; o > 0; o >>= 1) {
            da += __shfl_xor_sync(0xffffffffu, da, o);
            db += __shfl_xor_sync(0xffffffffu, db, o);
        }
        const float wa = expf(da);
        const float wb = expf(db);
        wsum += wa + wb;
#pragma unroll
        for (int k = 0; k < 8; k++) {
            acc[k].x += wa * xa[k].x + wb * xb[k].x;
            acc[k].y += wa * xa[k].y + wb * xb[k].y;
            acc[k].z += wa * xa[k].z + wb * xb[k].z;
            acc[k].w += wa * xa[k].w + wb * xb[k].w;
        }
    }
    // remainder: single row
    if (r < r1) {
        const float4* __restrict__ xr = X + (size_t)r * D4;
        float4 x[8];
        float dot = 0.f;
#pragma unroll
        for (int k = 0; k < 8; k++) {
            x[k] = __ldg(xr + lane + 32 * k);
            const float4 b = s_bw[lane + 32 * k];
            dot += x[k].x * b.x + x[k].y * b.y + x[k].z * b.z + x[k].w * b.w;
        }
#pragma unroll
        for (int o = 16; o > 0; o >>= 1) dot += __shfl_xor_sync(0xffffffffu, dot, o);
        const float w = expf(dot);
        wsum += w;
#pragma unroll
        for (int k = 0; k < 8; k++) {
            acc[k].x += w * x[k].x; acc[k].y += w * x[k].y;
            acc[k].z += w * x[k].z; acc[k].w += w * x[k].w;
        }
    }

#pragma unroll
    for (int k = 0; k < 8; k++) s_wacc[wid][lane + 32 * k] = acc[k];
    if (lane == 0) s_wsum[wid] = wsum;
    __syncthreads();

    float4 tot = make_float4(0.f, 0.f, 0.f, 0.f);
#pragma unroll
    for (int w = 0; w < 8; w++) {
        const float4 v = s_wacc[w][tid];
        tot.x += v.x; tot.y += v.y; tot.z += v.z; tot.w += v.w;
    }
    g_acc_part[mat][blockIdx.x][tid] = tot;
    if (tid == 0) {
        float ws = 0.f;
#pragma unroll
        for (int w = 0; w < 8; w++) ws += s_wsum[w];
        g_wsum_part[mat][blockIdx.x] = ws;
    }
}

// ---------------- k4a: first-level tree reduce of main-pass partials ----------------
// grid (4 colgroups, BG=16 bgroups, 2 mats) = 128 blocks, block 256.
// Each block reduces up to BPG=19 partial rows over 256 contiguous columns
// (coalesced, independent loads -> latency-tolerant).
__global__ void k4a_reduce() {
    const int colg = blockIdx.x, g = blockIdx.y, mat = blockIdx.z;
    const int col = colg * 256 + threadIdx.x;
    const float* __restrict__ ap = (const float*)g_acc_part[mat];
    const int b0 = g * BPG;
    float s = 0.f;
#pragma unroll
    for (int i = 0; i < BPG; i++) {
        const int b = b0 + i;
        if (b < K3B) s += ap[(size_t)b * D + col];
    }
    g_acc2[mat][g][col] = s;

    // parallel wsum partial: lanes of warp 0 on the colg==0 block
    if (colg == 0 && threadIdx.x < 32) {
        const int lane = threadIdx.x;
        float ws = 0.f;
        if (lane < BPG) {
            const int b = b0 + lane;
            if (b < K3B) ws = g_wsum_part[mat][b];
        }
#pragma unroll
        for (int o = 16; o > 0; o >>= 1) ws += __shfl_xor_sync(0xffffffffu, ws, o);
        if (lane == 0) g_wsum2[mat][g] = ws;
    }
}

// ---------------- k4b: second-level reduce -> g_vec = acc / wsum ----------------
// grid (8, 2), block 128
__global__ void k4b_reduce() {
    const int mat = blockIdx.y;
    const int col = blockIdx.x * 128 + threadIdx.x;
    float s = 0.f;
#pragma unroll
    for (int g = 0; g < BG; g++) s += g_acc2[mat][g][col];
    float ws = 0.f;
#pragma unroll
    for (int g = 0; g < BG; g++) ws += g_wsum2[mat][g];
    g_vec[mat][col] = s / ws;
}

// ---------------- k5: partial res = sum_output @ W_sum ----------------
// grid (4 colgroups, RC rowchunks of 64, 2 mats), block 256
__global__ void k5_res_partial(const float* __restrict__ Ws_in, const float* __restrict__ Ws_out) {
    const int colg = blockIdx.x, rc = blockIdx.y, mat = blockIdx.z;
    const float* __restrict__ W = mat ? Ws_out : Ws_in;
    __shared__ float s_v[64];
    const int tid = threadIdx.x;
    if (tid < 64) s_v[tid] = g_vec[mat][rc * 64 + tid];
    __syncthreads();
    const int col = colg * 256 + tid;
    const float* __restrict__ Wp = W + (size_t)(rc * 64) * D + col;
    float acc = 0.f;
#pragma unroll 16
    for (int r = 0; r < 64; r++) acc += s_v[r] * __ldg(Wp + (size_t)r * D);
    g_res_part[mat][rc][col] = acc;
}

// ---------------- k7: reduce attn partials + final elu(lin_W @ attn + b) ----------------
// grid 128, block 256 (8 warps, warp-per-output-row)
__global__ void k7_final(const float* __restrict__ linW, const float* __restrict__ linb,
                         float* __restrict__ out) {
    __shared__ float s_attn[2 * D];
    const int tid = threadIdx.x;
    for (int i = tid; i < 2 * D; i += 256) {
        const int m = i >> 10, c = i & (D - 1);
        float s = 0.f;
#pragma unroll
        for (int rc = 0; rc < RC; rc++) s += g_res_part[m][rc][c];
        s_attn[i] = s;
    }
    __syncthreads();

    const int lane = tid & 31, wid = tid >> 5;
    const int d = blockIdx.x * 8 + wid;
    const float4* __restrict__ row = (const float4*)(linW + (size_t)d * (2 * D));
    const float4* at = (const float4*)s_attn;
    float dot = 0.f;
#pragma unroll
    for (int k = 0; k < 16; k++) {
        const float4 a = __ldg(row + lane + 32 * k);
        const float4 b = at[lane + 32 * k];
        dot += a.x * b.x + a.y * b.y + a.z * b.z + a.w * b.w;
    }
#pragma unroll
    for (int o = 16; o > 0; o >>= 1) dot += __shfl_xor_sync(0xffffffffu, dot, o);
    if (lane == 0) {
        const float r = dot + linb[d];
        out[d] = r > 0.f ? r : expm1f(r);
    }
}

// ---------------- launch ----------------
extern "C" void kernel_launch(void* const* d_in, const int* in_sizes, int n_in,
                              void* d_out, int out_size) {
    const float* X_in   = (const float*)d_in[0];
    const float* X_out  = (const float*)d_in[1];
    const float* Wa_in  = (const float*)d_in[2];
    // d_in[3] = a_alpha_in  : unused (constant score offset cancels in softmax normalization)
    const float* b_in   = (const float*)d_in[4];
    const float* Ws_in  = (const float*)d_in[5];
    const float* Wa_out = (const float*)d_in[6];
    // d_in[7] = a_alpha_out : unused
    const float* b_out  = (const float*)d_in[8];
    const float* Ws_out = (const float*)d_in[9];
    const float* linW   = (const float*)d_in[10];
    const float* linb   = (const float*)d_in[11];
    const int N = in_sizes[0] / D;

    k1_bw_partial<<<dim3(4, RC, NMAT), 256>>>(Wa_in, b_in, Wa_out, b_out);
    k2_bw_reduce<<<dim3(4, NMAT), 256>>>();
    k3_main<<<dim3(K3B, NMAT), 256>>>(X_in, X_out, N);
    k4a_reduce<<<dim3(4, BG, NMAT), 256>>>();
    k4b_reduce<<<dim3(8, NMAT), 128>>>();
    k5_res_partial<<<dim3(4, RC, NMAT), 256>>>(Ws_in, Ws_out);
    k7_final<<<128, 256>>>(linW, linb, (float*)d_out);
}

// round 8
// speedup vs baseline: 1.1367x; 1.1367x over previous
#include <cuda_runtime.h>
#include <math.h>

#define D     1024
#define D4    256          // D / 4
#define NMAT  2
#define RC    16           // row chunks for the small matvec kernels (64 rows each)
#define K3B   296          // blocks per matrix for the main streaming pass
#define MAXBLK 304         // padded: rows [296,304) never written -> stay zero
#define BG    16           // reduction bgroups
#define BPG   19           // partials per bgroup (16*19 = 304, pad rows are zero)

// ---------------- static device scratch (no allocation allowed) ----------------
// NOTE: __device__ globals are zero-initialized; k3 writes only rows < K3B,
// so pad rows [K3B, MAXBLK) remain zero forever -> k4a needs no bounds guard.
__device__ float  g_bw_part[NMAT][RC][D];
__device__ float  g_bw[NMAT][D];
__device__ float4 g_acc_part[NMAT][MAXBLK][D4];
__device__ float  g_wsum_part[NMAT][MAXBLK];
__device__ float  g_acc2[NMAT][BG][D];
__device__ float  g_wsum2[NMAT][BG];
__device__ float  g_res_part[NMAT][RC][D];

// ---------------- k1: partial b_w = b_alpha^T @ W_alpha ----------------
// grid (4 colgroups, RC rowchunks of 64, 2 mats), block 256
__global__ void k1_bw_partial(const float* __restrict__ Wa_in,  const float* __restrict__ b_in,
                              const float* __restrict__ Wa_out, const float* __restrict__ b_out) {
    const int colg = blockIdx.x, rc = blockIdx.y, mat = blockIdx.z;
    const float* __restrict__ W  = mat ? Wa_out : Wa_in;
    const float* __restrict__ bv = mat ? b_out  : b_in;
    __shared__ float s_b[64];
    const int tid = threadIdx.x;
    if (tid < 64) s_b[tid] = bv[rc * 64 + tid];
    __syncthreads();
    const int col = colg * 256 + tid;
    const float* __restrict__ Wp = W + (size_t)(rc * 64) * D + col;
    float acc = 0.f;
#pragma unroll 16
    for (int r = 0; r < 64; r++) acc += s_b[r] * __ldg(Wp + (size_t)r * D);
    g_bw_part[mat][rc][col] = acc;
}

// ---------------- k2: reduce b_w partials ----------------
// grid (4, 2), block 256
__global__ void k2_bw_reduce() {
    const int mat = blockIdx.y;
    const int col = blockIdx.x * 256 + threadIdx.x;
    float s = 0.f;
#pragma unroll
    for (int rc = 0; rc < RC; rc++) s += g_bw_part[mat][rc][col];
    g_bw[mat][col] = s;
}

// ---------------- k3: fused main pass (2-row software pipeline) ----------------
// One read of X: per row j compute s = X_j . b_w, w = exp(s), acc += w * X_j, wsum += w.
// warp-per-row, float4 loads, two rows in flight (16 LDG.128/warp/iter), interleaved
// shfl chains. grid (K3B, 2), block 256 (8 warps)
__global__ void __launch_bounds__(256, 2)
k3_main(const float* __restrict__ Xin, const float* __restrict__ Xout, int N) {
    const int mat  = blockIdx.y;
    const float4* __restrict__ X = (const float4*)(mat ? Xout : Xin);
    const int tid  = threadIdx.x;
    const int lane = tid & 31;
    const int wid  = tid >> 5;

    __shared__ float4 s_bw[D4];
    __shared__ float4 s_wacc[8][D4];
    __shared__ float  s_wsum[8];

    s_bw[tid] = ((const float4*)g_bw[mat])[tid];

    const int rpb = (N + K3B - 1) / K3B;      // 169
    const int r0  = blockIdx.x * rpb;
    const int r1  = min(N, r0 + rpb);

    float4 acc[8];
#pragma unroll
    for (int k = 0; k < 8; k++) acc[k] = make_float4(0.f, 0.f, 0.f, 0.f);
    float wsum = 0.f;
    __syncthreads();

    int r = r0 + wid;
    // main: two rows per iteration -> 16 independent LDG.128, 2 interleaved shfl chains
    for (; r + 8 < r1; r += 16) {
        const float4* __restrict__ xra = X + (size_t)r * D4;
        const float4* __restrict__ xrb = X + (size_t)(r + 8) * D4;
        float4 xa[8], xb[8];
#pragma unroll
        for (int k = 0; k < 8; k++) xa[k] = __ldg(xra + lane + 32 * k);
#pragma unroll
        for (int k = 0; k < 8; k++) xb[k] = __ldg(xrb + lane + 32 * k);
        float da = 0.f, db = 0.f;
#pragma unroll
        for (int k = 0; k < 8; k++) {
            const float4 b = s_bw[lane + 32 * k];
            da += xa[k].x * b.x + xa[k].y * b.y + xa[k].z * b.z + xa[k].w * b.w;
            db += xb[k].x * b.x + xb[k].y * b.y + xb[k].z * b.z + xb[k].w * b.w;
        }
#pragma unroll
        for (int o = 16; o > 0; o >>= 1) {
            da += __shfl_xor_sync(0xffffffffu, da, o);
            db += __shfl_xor_sync(0xffffffffu, db, o);
        }
        const float wa = expf(da);
        const float wb = expf(db);
        wsum += wa + wb;
#pragma unroll
        for (int k = 0; k < 8; k++) {
            acc[k].x += wa * xa[k].x + wb * xb[k].x;
            acc[k].y += wa * xa[k].y + wb * xb[k].y;
            acc[k].z += wa * xa[k].z + wb * xb[k].z;
            acc[k].w += wa * xa[k].w + wb * xb[k].w;
        }
    }
    // remainder: single row
    if (r < r1) {
        const float4* __restrict__ xr = X + (size_t)r * D4;
        float4 x[8];
        float dot = 0.f;
#pragma unroll
        for (int k = 0; k < 8; k++) {
            x[k] = __ldg(xr + lane + 32 * k);
            const float4 b = s_bw[lane + 32 * k];
            dot += x[k].x * b.x + x[k].y * b.y + x[k].z * b.z + x[k].w * b.w;
        }
#pragma unroll
        for (int o = 16; o > 0; o >>= 1) dot += __shfl_xor_sync(0xffffffffu, dot, o);
        const float w = expf(dot);
        wsum += w;
#pragma unroll
        for (int k = 0; k < 8; k++) {
            acc[k].x += w * x[k].x; acc[k].y += w * x[k].y;
            acc[k].z += w * x[k].z; acc[k].w += w * x[k].w;
        }
    }

#pragma unroll
    for (int k = 0; k < 8; k++) s_wacc[wid][lane + 32 * k] = acc[k];
    if (lane == 0) s_wsum[wid] = wsum;
    __syncthreads();

    float4 tot = make_float4(0.f, 0.f, 0.f, 0.f);
#pragma unroll
    for (int w = 0; w < 8; w++) {
        const float4 v = s_wacc[w][tid];
        tot.x += v.x; tot.y += v.y; tot.z += v.z; tot.w += v.w;
    }
    g_acc_part[mat][blockIdx.x][tid] = tot;
    if (tid == 0) {
        float ws = 0.f;
#pragma unroll
        for (int w = 0; w < 8; w++) ws += s_wsum[w];
        g_wsum_part[mat][blockIdx.x] = ws;
    }
}

// ---------------- k4a: first-level tree reduce of main-pass partials ----------------
// grid (4 colgroups, BG=16 bgroups, 2 mats) = 128 blocks, block 256.
// Each block reduces BPG=19 partial rows over 256 contiguous columns.
// NO bounds guard: rows [296,304) are zero-initialized pad -> 19 independent
// unguarded loads per thread (high MLP).
__global__ void k4a_reduce() {
    const int colg = blockIdx.x, g = blockIdx.y, mat = blockIdx.z;
    const int col = colg * 256 + threadIdx.x;
    const float* __restrict__ ap = (const float*)g_acc_part[mat];
    const int b0 = g * BPG;
    float s = 0.f;
#pragma unroll
    for (int i = 0; i < BPG; i++) s += ap[(size_t)(b0 + i) * D + col];
    g_acc2[mat][g][col] = s;

    // parallel wsum partial: lanes of warp 0 on the colg==0 block (pad rows are 0)
    if (colg == 0 && threadIdx.x < 32) {
        const int lane = threadIdx.x;
        float ws = (lane < BPG) ? g_wsum_part[mat][b0 + lane] : 0.f;
#pragma unroll
        for (int o = 16; o > 0; o >>= 1) ws += __shfl_xor_sync(0xffffffffu, ws, o);
        if (lane == 0) g_wsum2[mat][g] = ws;
    }
}

// ---------------- k5: final vec reduce + partial res = (acc/wsum) @ W_sum ----------------
// grid (4 colgroups, RC rowchunks of 64, 2 mats), block 256.
// Each block recomputes its 64-entry slice of the normalized vector from g_acc2
// (k4b folded in), then does the matvec partial.
__global__ void k5_res_partial(const float* __restrict__ Ws_in, const float* __restrict__ Ws_out) {
    const int colg = blockIdx.x, rc = blockIdx.y, mat = blockIdx.z;
    const float* __restrict__ W = mat ? Ws_out : Ws_in;
    __shared__ float s_v[64];
    const int tid = threadIdx.x;
    if (tid < 64) {
        const int vc = rc * 64 + tid;
        float s = 0.f;
#pragma unroll
        for (int g = 0; g < BG; g++) s += g_acc2[mat][g][vc];
        float ws = 0.f;
#pragma unroll
        for (int g = 0; g < BG; g++) ws += g_wsum2[mat][g];
        s_v[tid] = s / ws;
    }
    __syncthreads();
    const int col = colg * 256 + tid;
    const float* __restrict__ Wp = W + (size_t)(rc * 64) * D + col;
    float acc = 0.f;
#pragma unroll 16
    for (int r = 0; r < 64; r++) acc += s_v[r] * __ldg(Wp + (size_t)r * D);
    g_res_part[mat][rc][col] = acc;
}

// ---------------- k7: reduce attn partials + final elu(lin_W @ attn + b) ----------------
// grid 128, block 256 (8 warps, warp-per-output-row)
__global__ void k7_final(const float* __restrict__ linW, const float* __restrict__ linb,
                         float* __restrict__ out) {
    __shared__ float s_attn[2 * D];
    const int tid = threadIdx.x;
    for (int i = tid; i < 2 * D; i += 256) {
        const int m = i >> 10, c = i & (D - 1);
        float s = 0.f;
#pragma unroll
        for (int rc = 0; rc < RC; rc++) s += g_res_part[m][rc][c];
        s_attn[i] = s;
    }
    __syncthreads();

    const int lane = tid & 31, wid = tid >> 5;
    const int d = blockIdx.x * 8 + wid;
    const float4* __restrict__ row = (const float4*)(linW + (size_t)d * (2 * D));
    const float4* at = (const float4*)s_attn;
    float dot = 0.f;
#pragma unroll
    for (int k = 0; k < 16; k++) {
        const float4 a = __ldg(row + lane + 32 * k);
        const float4 b = at[lane + 32 * k];
        dot += a.x * b.x + a.y * b.y + a.z * b.z + a.w * b.w;
    }
#pragma unroll
    for (int o = 16; o > 0; o >>= 1) dot += __shfl_xor_sync(0xffffffffu, dot, o);
    if (lane == 0) {
        const float r = dot + linb[d];
        out[d] = r > 0.f ? r : expm1f(r);
    }
}

// ---------------- launch ----------------
extern "C" void kernel_launch(void* const* d_in, const int* in_sizes, int n_in,
                              void* d_out, int out_size) {
    const float* X_in   = (const float*)d_in[0];
    const float* X_out  = (const float*)d_in[1];
    const float* Wa_in  = (const float*)d_in[2];
    // d_in[3] = a_alpha_in  : unused (constant score offset cancels in softmax normalization)
    const float* b_in   = (const float*)d_in[4];
    const float* Ws_in  = (const float*)d_in[5];
    const float* Wa_out = (const float*)d_in[6];
    // d_in[7] = a_alpha_out : unused
    const float* b_out  = (const float*)d_in[8];
    const float* Ws_out = (const float*)d_in[9];
    const float* linW   = (const float*)d_in[10];
    const float* linb   = (const float*)d_in[11];
    const int N = in_sizes[0] / D;

    k1_bw_partial<<<dim3(4, RC, NMAT), 256>>>(Wa_in, b_in, Wa_out, b_out);
    k2_bw_reduce<<<dim3(4, NMAT), 256>>>();
    k3_main<<<dim3(K3B, NMAT), 256>>>(X_in, X_out, N);
    k4a_reduce<<<dim3(4, BG, NMAT), 256>>>();
    k5_res_partial<<<dim3(4, RC, NMAT), 256>>>(Ws_in, Ws_out);
    k7_final<<<128, 256>>>(linW, linb, (float*)d_out);
}